// round 9
// baseline (speedup 1.0000x reference)
#include <cuda_runtime.h>
#include <cuda_bf16.h>
#include <cstdint>

typedef unsigned long long ull;

// ---------------- problem constants ----------------
#define BATCH 64
#define DIN   176
#define HID   512
#define G4    2048          // 4*HID
#define T_ENC 1025          // 1 + 1024
#define T_DEC 1023          // TTGT - 1
#define MROWS_MAX (BATCH * T_ENC)   // 65600
#define MD_ROWS   (BATCH * T_DEC)   // 65472

// ---------------- scratch (static device globals; no cudaMalloc allowed) ----
__device__ float g_gx[(size_t)MROWS_MAX * G4];     // per-layer gx (fp32)
#define ABUF_ROWS (MROWS_MAX + 128)
__device__ __nv_bfloat16 g_AH[(size_t)ABUF_ROWS * 512];   // A operand hi
__device__ __nv_bfloat16 g_AL[(size_t)ABUF_ROWS * 512];   // A operand lo
#define MBUF_ROWS (MD_ROWS + 128)
__device__ __nv_bfloat16 g_MH[(size_t)MBUF_ROWS * 256];   // hmid hi
__device__ __nv_bfloat16 g_ML[(size_t)MBUF_ROWS * 256];   // hmid lo
__device__ __nv_bfloat16 g_WHb[2048 * 512];               // W operand hi
__device__ __nv_bfloat16 g_WLb[2048 * 512];               // W operand lo
__device__ float g_hpub[2 * BATCH * HID];
__device__ float g_hT0[BATCH * HID], g_cT0[BATCH * HID];
__device__ float g_hT1[BATCH * HID], g_cT1[BATCH * HID];
__device__ float g_hTd[BATCH * HID], g_cTd[BATCH * HID];
__device__ unsigned g_bar[128];                           // per-CTA step flags

// ---------------- helpers ----------------
__device__ __forceinline__ void bf16_split(float v, __nv_bfloat16& hi, __nv_bfloat16& lo) {
    hi = __float2bfloat16(v);
    lo = __float2bfloat16(v - __bfloat162float(hi));
}

__device__ __forceinline__ uint32_t smem_to_u32(const void* p) {
    uint32_t a;
    asm("{ .reg .u64 t; cvta.to.shared.u64 t, %1; cvt.u32.u64 %0, t; }" : "=r"(a) : "l"(p));
    return a;
}

// HMMA m16n8k16 bf16 (non-arch-gated PTX; runs on sm_103 base target)
__device__ __forceinline__ void mma16816(float* d, const uint32_t* a, const uint32_t* b) {
    asm volatile(
        "mma.sync.aligned.m16n8k16.row.col.f32.bf16.bf16.f32 "
        "{%0,%1,%2,%3}, {%4,%5,%6,%7}, {%8,%9}, {%0,%1,%2,%3};"
        : "+f"(d[0]), "+f"(d[1]), "+f"(d[2]), "+f"(d[3])
        : "r"(a[0]), "r"(a[1]), "r"(a[2]), "r"(a[3]), "r"(b[0]), "r"(b[1]));
}

// cp.async 16B (LDGSTS; sm_80 PTX, non-gated)
__device__ __forceinline__ void cpasync16(uint32_t s, const void* g) {
    asm volatile("cp.async.cg.shared.global [%0], [%1], 16;" :: "r"(s), "l"(g));
}
#define CP_COMMIT() asm volatile("cp.async.commit_group;" ::: "memory")
#define CP_WAIT1()  asm volatile("cp.async.wait_group 1;" ::: "memory")

// ---------------- small utility kernels ----------------
__global__ void reset_bar_kernel(unsigned* bar) {
    if (threadIdx.x < 128) bar[threadIdx.x] = 0u;
}

// padded-shifted input -> bf16 hi/lo, layout [b][t][192] (cols 176..191 zero)
__global__ void pad_shift_bf16_kernel(const float* __restrict__ src,
                                      __nv_bfloat16* __restrict__ dH,
                                      __nv_bfloat16* __restrict__ dL,
                                      int Tsrc, int Tpad, int Tcopy) {
    long n = (long)BATCH * Tpad * 192;
    long i = (long)blockIdx.x * blockDim.x + threadIdx.x;
    if (i >= n) return;
    int d = (int)(i % 192);
    long bt = i / 192;
    int t = (int)(bt % Tpad);
    int b = (int)(bt / Tpad);
    float v = (d < DIN && t > 0 && t <= Tcopy) ? src[((long)b * Tsrc + (t - 1)) * DIN + d] : 0.f;
    __nv_bfloat16 hi, lo; bf16_split(v, hi, lo);
    dH[i] = hi; dL[i] = lo;
}

// W (N x K fp32) -> WH/WL (Npad x kpad bf16, zero padded)
__global__ void conv_w_kernel(const float* __restrict__ W,
                              __nv_bfloat16* __restrict__ WH, __nv_bfloat16* __restrict__ WL,
                              int N, int K, int kpad, int Npad) {
    long n = (long)Npad * kpad;
    long i = (long)blockIdx.x * blockDim.x + threadIdx.x;
    if (i >= n) return;
    int row = (int)(i / kpad), c = (int)(i % kpad);
    float v = (row < N && c < K) ? W[(size_t)row * K + c] : 0.f;
    __nv_bfloat16 hi, lo; bf16_split(v, hi, lo);
    WH[i] = hi; WL[i] = lo;
}

__global__ void zero_t0_kernel(float* __restrict__ out) {
    int i = blockIdx.x * blockDim.x + threadIdx.x;
    if (i < BATCH * DIN) {
        int b = i / DIN, d = i % DIN;
        out[(size_t)b * 1024 * DIN + d] = 0.f;
    }
}

// ---------------- HMMA GEMM (cp.async 2-stage pipelined) -------------------
// Identical to round-8 passing version.
#define SOFF_AL  5120
#define SOFF_BH  10240
#define SOFF_BL  12800
#define STG_ELEMS 15360
#define MMA_SMEM_BYTES (2 * STG_ELEMS * 2)   // 61440

__global__ void __launch_bounds__(256)
mma_gemm_kernel(const __nv_bfloat16* __restrict__ AH, const __nv_bfloat16* __restrict__ AL,
                const __nv_bfloat16* __restrict__ WH, const __nv_bfloat16* __restrict__ WL,
                int kpad, int nChunks,
                const float* __restrict__ b1, const float* __restrict__ b2,
                float* __restrict__ Cf, __nv_bfloat16* __restrict__ CH,
                __nv_bfloat16* __restrict__ CL,
                int ldC, int M, int Nreal, int relu, int remapT) {
    extern __shared__ __align__(16) __nv_bfloat16 smbuf[];
    const uint32_t sb = smem_to_u32(smbuf);

    const int tid  = threadIdx.x;
    const int wid  = tid >> 5, lane = tid & 31;
    const int g    = lane >> 2, tg = lane & 3;
    const int m0   = (wid & 3) * 32;
    const int n0   = (wid >> 2) * 32;
    const int row0 = blockIdx.y * 128;
    const int col0 = blockIdx.x * 64;

    const int ar0 = tid >> 2, aseg = tid & 3;
    const int br  = tid >> 2, bseg = tid & 3;

    float d[2][4][4];
#pragma unroll
    for (int mi = 0; mi < 2; mi++)
#pragma unroll
        for (int ni = 0; ni < 4; ni++)
#pragma unroll
            for (int q = 0; q < 4; q++) d[mi][ni][q] = 0.f;

    auto load_chunk = [&](int ch, int stg) {
        const int kbase = ch * 32;
        const uint32_t base = sb + stg * (STG_ELEMS * 2);
#pragma unroll
        for (int i = 0; i < 2; i++) {
            int r = ar0 + i * 64;
            size_t go = (size_t)(row0 + r) * kpad + kbase + aseg * 8;
            uint32_t so = base + (r * 40 + aseg * 8) * 2;
            cpasync16(so, AH + go);
            cpasync16(so + SOFF_AL * 2, AL + go);
        }
        {
            size_t go = (size_t)(col0 + br) * kpad + kbase + bseg * 8;
            uint32_t so = base + (SOFF_BH + br * 40 + bseg * 8) * 2;
            cpasync16(so, WH + go);
            cpasync16(so + (SOFF_BL - SOFF_BH) * 2, WL + go);
        }
    };

    load_chunk(0, 0);
    CP_COMMIT();

    for (int ch = 0; ch < nChunks; ch++) {
        const int cur = ch & 1;
        if (ch + 1 < nChunks) load_chunk(ch + 1, cur ^ 1);
        CP_COMMIT();
        CP_WAIT1();
        __syncthreads();

        const __nv_bfloat16* sAH = smbuf + cur * STG_ELEMS;
        const __nv_bfloat16* sAL = sAH + SOFF_AL;
        const __nv_bfloat16* sBH = smbuf + cur * STG_ELEMS + SOFF_BH;
        const __nv_bfloat16* sBL = smbuf + cur * STG_ELEMS + SOFF_BL;

#pragma unroll
        for (int ks = 0; ks < 2; ks++) {
            const int kb = ks * 16;
            uint32_t aH[2][4], aL[2][4], bH[4][2], bL[4][2];
#pragma unroll
            for (int mi = 0; mi < 2; mi++) {
                int r = m0 + mi * 16 + g;
                aH[mi][0] = *(const uint32_t*)&sAH[r * 40 + kb + 2 * tg];
                aH[mi][1] = *(const uint32_t*)&sAH[(r + 8) * 40 + kb + 2 * tg];
                aH[mi][2] = *(const uint32_t*)&sAH[r * 40 + kb + 2 * tg + 8];
                aH[mi][3] = *(const uint32_t*)&sAH[(r + 8) * 40 + kb + 2 * tg + 8];
                aL[mi][0] = *(const uint32_t*)&sAL[r * 40 + kb + 2 * tg];
                aL[mi][1] = *(const uint32_t*)&sAL[(r + 8) * 40 + kb + 2 * tg];
                aL[mi][2] = *(const uint32_t*)&sAL[r * 40 + kb + 2 * tg + 8];
                aL[mi][3] = *(const uint32_t*)&sAL[(r + 8) * 40 + kb + 2 * tg + 8];
            }
#pragma unroll
            for (int ni = 0; ni < 4; ni++) {
                int r = n0 + ni * 8 + g;
                bH[ni][0] = *(const uint32_t*)&sBH[r * 40 + kb + 2 * tg];
                bH[ni][1] = *(const uint32_t*)&sBH[r * 40 + kb + 2 * tg + 8];
                bL[ni][0] = *(const uint32_t*)&sBL[r * 40 + kb + 2 * tg];
                bL[ni][1] = *(const uint32_t*)&sBL[r * 40 + kb + 2 * tg + 8];
            }
#pragma unroll
            for (int mi = 0; mi < 2; mi++)
#pragma unroll
                for (int ni = 0; ni < 4; ni++) {
                    mma16816(d[mi][ni], aH[mi], bH[ni]);
                    mma16816(d[mi][ni], aL[mi], bH[ni]);
                    mma16816(d[mi][ni], aH[mi], bL[ni]);
                }
        }
        __syncthreads();
    }

#pragma unroll
    for (int mi = 0; mi < 2; mi++) {
#pragma unroll
        for (int rr = 0; rr < 2; rr++) {
            int r = row0 + m0 + mi * 16 + g + rr * 8;
            if (r >= M) continue;
            size_t rowbase;
            if (remapT > 0) {
                int bb = r / remapT, tt = r - bb * remapT;
                rowbase = ((size_t)bb * (remapT + 1) + tt + 1) * (size_t)ldC;
            } else {
                rowbase = (size_t)r * ldC;
            }
#pragma unroll
            for (int ni = 0; ni < 4; ni++) {
#pragma unroll
                for (int cc = 0; cc < 2; cc++) {
                    int col = col0 + n0 + ni * 8 + 2 * tg + cc;
                    if (col >= Nreal) continue;
                    float v = d[mi][ni][rr * 2 + cc]
                            + (b1 ? __ldg(b1 + col) : 0.f) + (b2 ? __ldg(b2 + col) : 0.f);
                    if (relu) v = fmaxf(v, 0.f);
                    if (Cf) Cf[rowbase + col] = v;
                    if (CH) {
                        __nv_bfloat16 hi, lo; bf16_split(v, hi, lo);
                        CH[rowbase + col] = hi;
                        CL[rowbase + col] = lo;
                    }
                }
            }
        }
    }
}

// ---------------- persistent LSTM scan -------------------------------------
// Round-8 proven structure; barrier replaced with distributed per-CTA flags:
// arrive = st.release.gpu to own slot, wait = 32-lane coalesced ld.acquire
// poll of all 32 flags in the batch group (no LTS atomic serialization).
#define SCAN_H_ULL   (512 * 16)
#define SCAN_RED_ULL (8 * 32 * 17)
#define SCAN_SMEM_BYTES ((SCAN_H_ULL + SCAN_RED_ULL) * 8)

__device__ __forceinline__ ull pack2(float x, float y) {
    ull r; asm("mov.b64 %0, {%1, %2};" : "=l"(r) : "f"(x), "f"(y)); return r;
}
__device__ __forceinline__ void fma2(ull& a, ull w, ull h) {
    asm("fma.rn.f32x2 %0, %1, %2, %0;" : "+l"(a) : "l"(w), "l"(h));
}
__device__ __forceinline__ float sigf(float x) { return 1.f / (1.f + expf(-x)); }

__device__ __forceinline__ void group_barrier(unsigned* flags, int bg, int ht,
                                              unsigned step) {
    __threadfence();          // release this CTA's global writes
    __syncthreads();          // all threads fenced
    if (threadIdx.x < 32) {
        unsigned* myf = flags + bg * 32 + ht;
        if (threadIdx.x == 0)
            asm volatile("st.release.gpu.global.u32 [%0], %1;"
                         :: "l"(myf), "r"(step) : "memory");
        const unsigned* pf = flags + bg * 32 + threadIdx.x;
        unsigned v;
        do {
            asm volatile("ld.acquire.gpu.global.u32 %0, [%1];"
                         : "=r"(v) : "l"(pf) : "memory");
        } while (!__all_sync(0xffffffffu, v >= step));
    }
    __syncthreads();
}

__global__ void __launch_bounds__(256, 1)
lstm_scan_kernel(const float* __restrict__ gx, const float* __restrict__ Whh,
                 const float* __restrict__ h0, const float* __restrict__ c0,
                 __nv_bfloat16* __restrict__ hsH, __nv_bfloat16* __restrict__ hsL,
                 float* __restrict__ hT_out, float* __restrict__ cT_out,
                 float* __restrict__ hpub, unsigned* __restrict__ bar, int T) {
    extern __shared__ __align__(16) ull smu[];
    ull* h_d = smu;
    ull* red = smu + SCAN_H_ULL;

    const int tid = threadIdx.x;
    const int bg = blockIdx.x >> 5;
    const int ht = blockIdx.x & 31;
    const int B0 = bg * 16;
    const int J0 = ht * 16;
    const int w = tid >> 5;
    const int l = tid & 31;

    ull wreg[64];
    {
        const int r0 = 2 * l;
        const int g = r0 >> 4, j = r0 & 15;
        const float* p0 = Whh + ((size_t)(g * 512 + J0 + j)) * 512 + w * 64;
        const float* p1 = p0 + 512;
#pragma unroll
        for (int kk = 0; kk < 64; kk++)
            wreg[kk] = pack2(__ldg(p0 + kk), __ldg(p1 + kk));
    }

    const int ub = tid >> 4;
    const int uj = tid & 15;
    float cval = c0 ? c0[(B0 + ub) * 512 + J0 + uj] : 0.f;
    float hval = h0 ? h0[(B0 + ub) * 512 + J0 + uj] : 0.f;
    hpub[32768 + (B0 + ub) * 512 + J0 + uj] = hval;

    unsigned nbar = 1;
    group_barrier(bar, bg, ht, nbar);

    const int p1b = tid & 15;
    const int p1k = tid >> 4;

    const float* gxrow = gx + ((size_t)(B0 + ub) * T) * G4 + J0 + uj;
    __nv_bfloat16* hH = hsH ? hsH + ((size_t)(B0 + ub) * T) * 512 + J0 + uj : nullptr;
    __nv_bfloat16* hL = hsL ? hsL + ((size_t)(B0 + ub) * T) * 512 + J0 + uj : nullptr;

    // prefetch gx for t=0
    float pgi = gxrow[0], pgf = gxrow[512], pgg = gxrow[1024], pgo = gxrow[1536];

    for (int t = 0; t < T; ++t) {
        const float* hsrc = hpub + (((t + 1) & 1) << 15);
#pragma unroll
        for (int i = 0; i < 8; ++i) {
            int kq = p1k + (i << 4);
            float4 hv = __ldcg((const float4*)(hsrc + (B0 + p1b) * 512 + (kq << 2)));
            h_d[((kq << 2) + 0) * 16 + p1b] = pack2(hv.x, hv.x);
            h_d[((kq << 2) + 1) * 16 + p1b] = pack2(hv.y, hv.y);
            h_d[((kq << 2) + 2) * 16 + p1b] = pack2(hv.z, hv.z);
            h_d[((kq << 2) + 3) * 16 + p1b] = pack2(hv.w, hv.w);
        }
        __syncthreads();

        ull pacc[16];
#pragma unroll
        for (int b = 0; b < 16; b++) pacc[b] = 0ull;

        const ull* hk = h_d + (w << 6) * 16;
#pragma unroll
        for (int kk = 0; kk < 64; ++kk) {
#pragma unroll
            for (int b2 = 0; b2 < 16; b2 += 2) {
                ulonglong2 h2 = *(const ulonglong2*)(hk + kk * 16 + b2);
                fma2(pacc[b2],     wreg[kk], h2.x);
                fma2(pacc[b2 + 1], wreg[kk], h2.y);
            }
        }

        {
            ull* rp = red + (w * 32 + l) * 17;
#pragma unroll
            for (int b = 0; b < 16; b++) rp[b] = pacc[b];
        }
        __syncthreads();

        const float* fred = (const float*)red;
        float gsum[4];
#pragma unroll
        for (int g = 0; g < 4; g++) {
            const int ll = g * 8 + (uj >> 1);
            const int comp = uj & 1;
            float v = 0.f;
#pragma unroll
            for (int s2 = 0; s2 < 8; s2++)
                v += fred[2 * (((s2 << 5) + ll) * 17 + ub) + comp];
            gsum[g] = v;
        }
        float gi = gsum[0] + pgi, gf = gsum[1] + pgf;
        float gg = gsum[2] + pgg, go = gsum[3] + pgo;

        float ig = sigf(gi), fg = sigf(gf), og_ = sigf(go), gt = tanhf(gg);
        cval = fg * cval + ig * gt;
        hval = og_ * tanhf(cval);

        hpub[((t & 1) << 15) + (B0 + ub) * 512 + J0 + uj] = hval;
        if (hH) {
            __nv_bfloat16 hi, lo; bf16_split(hval, hi, lo);
            *hH = hi; *hL = lo; hH += 512; hL += 512;
        }
        gxrow += G4;

        // next-step gx prefetch BEFORE the barrier (input-only, bounds-guarded)
        if (t + 1 < T) {
            pgi = gxrow[0]; pgf = gxrow[512];
            pgg = gxrow[1024]; pgo = gxrow[1536];
        }

        ++nbar;
        group_barrier(bar, bg, ht, nbar);
    }

    hT_out[(B0 + ub) * 512 + J0 + uj] = hval;
    cT_out[(B0 + ub) * 512 + J0 + uj] = cval;
}

// ---------------- host orchestration ----------------
static __nv_bfloat16 *s_AH, *s_AL, *s_MH, *s_ML, *s_WH, *s_WL;

static void launch_mma(const __nv_bfloat16* AH, const __nv_bfloat16* AL,
                       int kpad, const float* b1, const float* b2,
                       float* Cf, __nv_bfloat16* CH, __nv_bfloat16* CL,
                       int ldC, int M, int Nreal, int relu, int remapT) {
    int mt = (M + 127) / 128;
    int nt = (Nreal + 63) / 64;
    int nChunks = kpad / 32;
    mma_gemm_kernel<<<dim3(nt, mt), 256, MMA_SMEM_BYTES>>>(
        AH, AL, s_WH, s_WL, kpad, nChunks, b1, b2, Cf, CH, CL, ldC, M, Nreal, relu, remapT);
}

static void launch_convw(const float* W, int N, int K, int kpad) {
    int Npad = ((N + 63) / 64) * 64;
    long n = (long)Npad * kpad;
    conv_w_kernel<<<(int)((n + 255) / 256), 256>>>(W, s_WH, s_WL, N, K, kpad, Npad);
}

extern "C" void kernel_launch(void* const* d_in, const int* in_sizes, int n_in,
                              void* d_out, int out_size) {
    (void)in_sizes; (void)n_in; (void)out_size;
    const float* x     = (const float*)d_in[0];
    const float* y     = (const float*)d_in[1];
    const float* eWih0 = (const float*)d_in[2];
    const float* eWhh0 = (const float*)d_in[3];
    const float* ebih0 = (const float*)d_in[4];
    const float* ebhh0 = (const float*)d_in[5];
    const float* eWih1 = (const float*)d_in[6];
    const float* eWhh1 = (const float*)d_in[7];
    const float* ebih1 = (const float*)d_in[8];
    const float* ebhh1 = (const float*)d_in[9];
    const float* dWih0 = (const float*)d_in[10];
    const float* dWhh0 = (const float*)d_in[11];
    const float* dbih0 = (const float*)d_in[12];
    const float* dbhh0 = (const float*)d_in[13];
    const float* dWih1 = (const float*)d_in[14];
    const float* dWhh1 = (const float*)d_in[15];
    const float* dbih1 = (const float*)d_in[16];
    const float* dbhh1 = (const float*)d_in[17];
    const float* clsW1 = (const float*)d_in[18];
    const float* clsb1 = (const float*)d_in[19];
    const float* clsW2 = (const float*)d_in[20];
    const float* clsb2 = (const float*)d_in[21];
    float* out = (float*)d_out;

    float *gx, *hpub, *hT0, *cT0, *hT1, *cT1, *hTd, *cTd;
    unsigned* bar;
    cudaGetSymbolAddress((void**)&gx,   g_gx);
    cudaGetSymbolAddress((void**)&hpub, g_hpub);
    cudaGetSymbolAddress((void**)&hT0,  g_hT0);
    cudaGetSymbolAddress((void**)&cT0,  g_cT0);
    cudaGetSymbolAddress((void**)&hT1,  g_hT1);
    cudaGetSymbolAddress((void**)&cT1,  g_cT1);
    cudaGetSymbolAddress((void**)&hTd,  g_hTd);
    cudaGetSymbolAddress((void**)&cTd,  g_cTd);
    cudaGetSymbolAddress((void**)&bar,  g_bar);
    cudaGetSymbolAddress((void**)&s_AH, g_AH);
    cudaGetSymbolAddress((void**)&s_AL, g_AL);
    cudaGetSymbolAddress((void**)&s_MH, g_MH);
    cudaGetSymbolAddress((void**)&s_ML, g_ML);
    cudaGetSymbolAddress((void**)&s_WH, g_WHb);
    cudaGetSymbolAddress((void**)&s_WL, g_WLb);

    cudaFuncSetAttribute(lstm_scan_kernel,
                         cudaFuncAttributeMaxDynamicSharedMemorySize, SCAN_SMEM_BYTES);
    cudaFuncSetAttribute(mma_gemm_kernel,
                         cudaFuncAttributeMaxDynamicSharedMemorySize, MMA_SMEM_BYTES);

    const int ME  = MROWS_MAX;   // 65600
    const int MDN = MD_ROWS;     // 65472

    // ---------------- encoder ----------------
    {
        long n = (long)BATCH * T_ENC * 192;
        pad_shift_bf16_kernel<<<(int)((n + 255) / 256), 256>>>(x, s_AH, s_AL, 1024, T_ENC, 1024);
    }
    launch_convw(eWih0, G4, DIN, 192);
    launch_mma(s_AH, s_AL, 192, ebih0, ebhh0, gx, nullptr, nullptr, G4, ME, G4, 0, 0);
    reset_bar_kernel<<<1, 128>>>(bar);
    lstm_scan_kernel<<<128, 256, SCAN_SMEM_BYTES>>>(gx, eWhh0, nullptr, nullptr,
                                                    s_AH, s_AL, hT0, cT0, hpub, bar, T_ENC);
    launch_convw(eWih1, G4, HID, 512);
    launch_mma(s_AH, s_AL, 512, ebih1, ebhh1, gx, nullptr, nullptr, G4, ME, G4, 0, 0);
    reset_bar_kernel<<<1, 128>>>(bar);
    lstm_scan_kernel<<<128, 256, SCAN_SMEM_BYTES>>>(gx, eWhh1, nullptr, nullptr,
                                                    nullptr, nullptr, hT1, cT1, hpub, bar, T_ENC);

    // ---------------- decoder ----------------
    {
        long n = (long)BATCH * T_DEC * 192;
        pad_shift_bf16_kernel<<<(int)((n + 255) / 256), 256>>>(y, s_AH, s_AL, 1024, T_DEC, 1022);
    }
    launch_convw(dWih0, G4, DIN, 192);
    launch_mma(s_AH, s_AL, 192, dbih0, dbhh0, gx, nullptr, nullptr, G4, MDN, G4, 0, 0);
    reset_bar_kernel<<<1, 128>>>(bar);
    lstm_scan_kernel<<<128, 256, SCAN_SMEM_BYTES>>>(gx, dWhh0, hT0, cT0,
                                                    s_AH, s_AL, hTd, cTd, hpub, bar, T_DEC);
    launch_convw(dWih1, G4, HID, 512);
    launch_mma(s_AH, s_AL, 512, dbih1, dbhh1, gx, nullptr, nullptr, G4, MDN, G4, 0, 0);
    reset_bar_kernel<<<1, 128>>>(bar);
    lstm_scan_kernel<<<128, 256, SCAN_SMEM_BYTES>>>(gx, dWhh1, hT1, cT1,
                                                    s_AH, s_AL, hTd, cTd, hpub, bar, T_DEC);

    // ---------------- classifier ----------------
    launch_convw(clsW1, 256, HID, 512);
    launch_mma(s_AH, s_AL, 512, clsb1, nullptr, nullptr, s_MH, s_ML, 256, MDN, 256, 1, 0);
    launch_convw(clsW2, DIN, 256, 256);
    launch_mma(s_MH, s_ML, 256, clsb2, nullptr, out, nullptr, nullptr, DIN, MDN, DIN, 0, T_DEC);
    zero_t0_kernel<<<(BATCH * DIN + 255) / 256, 256>>>(out);
}

// round 10
// speedup vs baseline: 1.7376x; 1.7376x over previous
#include <cuda_runtime.h>
#include <cuda_bf16.h>
#include <cstdint>

typedef unsigned long long ull;

// ---------------- problem constants ----------------
#define BATCH 64
#define DIN   176
#define HID   512
#define G4    2048          // 4*HID
#define T_ENC 1025          // 1 + 1024
#define T_DEC 1023          // TTGT - 1
#define MROWS_MAX (BATCH * T_ENC)   // 65600
#define MD_ROWS   (BATCH * T_DEC)   // 65472

// ---------------- scratch (static device globals; no cudaMalloc allowed) ----
__device__ float g_gx[(size_t)MROWS_MAX * G4];     // per-layer gx (fp32)
#define ABUF_ROWS (MROWS_MAX + 128)
__device__ __nv_bfloat16 g_AH[(size_t)ABUF_ROWS * 512];   // A operand hi
__device__ __nv_bfloat16 g_AL[(size_t)ABUF_ROWS * 512];   // A operand lo
#define MBUF_ROWS (MD_ROWS + 128)
__device__ __nv_bfloat16 g_MH[(size_t)MBUF_ROWS * 256];   // hmid hi
__device__ __nv_bfloat16 g_ML[(size_t)MBUF_ROWS * 256];   // hmid lo
__device__ __nv_bfloat16 g_WHb[2048 * 512];               // W operand hi
__device__ __nv_bfloat16 g_WLb[2048 * 512];               // W operand lo
__device__ float g_hpub[2 * BATCH * HID];
__device__ float g_hT0[BATCH * HID], g_cT0[BATCH * HID];
__device__ float g_hT1[BATCH * HID], g_cT1[BATCH * HID];
__device__ float g_hTd[BATCH * HID], g_cTd[BATCH * HID];
__device__ unsigned g_bar[4];

// ---------------- helpers ----------------
__device__ __forceinline__ void bf16_split(float v, __nv_bfloat16& hi, __nv_bfloat16& lo) {
    hi = __float2bfloat16(v);
    lo = __float2bfloat16(v - __bfloat162float(hi));
}

__device__ __forceinline__ uint32_t smem_to_u32(const void* p) {
    uint32_t a;
    asm("{ .reg .u64 t; cvta.to.shared.u64 t, %1; cvt.u32.u64 %0, t; }" : "=r"(a) : "l"(p));
    return a;
}

// HMMA m16n8k16 bf16 (non-arch-gated PTX; runs on sm_103 base target)
__device__ __forceinline__ void mma16816(float* d, const uint32_t* a, const uint32_t* b) {
    asm volatile(
        "mma.sync.aligned.m16n8k16.row.col.f32.bf16.bf16.f32 "
        "{%0,%1,%2,%3}, {%4,%5,%6,%7}, {%8,%9}, {%0,%1,%2,%3};"
        : "+f"(d[0]), "+f"(d[1]), "+f"(d[2]), "+f"(d[3])
        : "r"(a[0]), "r"(a[1]), "r"(a[2]), "r"(a[3]), "r"(b[0]), "r"(b[1]));
}

// cp.async 16B (LDGSTS; sm_80 PTX, non-gated)
__device__ __forceinline__ void cpasync16(uint32_t s, const void* g) {
    asm volatile("cp.async.cg.shared.global [%0], [%1], 16;" :: "r"(s), "l"(g));
}
#define CP_COMMIT() asm volatile("cp.async.commit_group;" ::: "memory")
#define CP_WAIT1()  asm volatile("cp.async.wait_group 1;" ::: "memory")

// ---------------- small utility kernels ----------------
__global__ void reset_bar_kernel(unsigned* bar) {
    if (threadIdx.x < 4) bar[threadIdx.x] = 0u;
}

// padded-shifted input -> bf16 hi/lo, layout [b][t][192] (cols 176..191 zero)
__global__ void pad_shift_bf16_kernel(const float* __restrict__ src,
                                      __nv_bfloat16* __restrict__ dH,
                                      __nv_bfloat16* __restrict__ dL,
                                      int Tsrc, int Tpad, int Tcopy) {
    long n = (long)BATCH * Tpad * 192;
    long i = (long)blockIdx.x * blockDim.x + threadIdx.x;
    if (i >= n) return;
    int d = (int)(i % 192);
    long bt = i / 192;
    int t = (int)(bt % Tpad);
    int b = (int)(bt / Tpad);
    float v = (d < DIN && t > 0 && t <= Tcopy) ? src[((long)b * Tsrc + (t - 1)) * DIN + d] : 0.f;
    __nv_bfloat16 hi, lo; bf16_split(v, hi, lo);
    dH[i] = hi; dL[i] = lo;
}

// W (N x K fp32) -> WH/WL (Npad x kpad bf16, zero padded)
__global__ void conv_w_kernel(const float* __restrict__ W,
                              __nv_bfloat16* __restrict__ WH, __nv_bfloat16* __restrict__ WL,
                              int N, int K, int kpad, int Npad) {
    long n = (long)Npad * kpad;
    long i = (long)blockIdx.x * blockDim.x + threadIdx.x;
    if (i >= n) return;
    int row = (int)(i / kpad), c = (int)(i % kpad);
    float v = (row < N && c < K) ? W[(size_t)row * K + c] : 0.f;
    __nv_bfloat16 hi, lo; bf16_split(v, hi, lo);
    WH[i] = hi; WL[i] = lo;
}

__global__ void zero_t0_kernel(float* __restrict__ out) {
    int i = blockIdx.x * blockDim.x + threadIdx.x;
    if (i < BATCH * DIN) {
        int b = i / DIN, d = i % DIN;
        out[(size_t)b * 1024 * DIN + d] = 0.f;
    }
}

// ---------------- HMMA GEMM (cp.async 2-stage pipelined; round-8 proven) ---
#define SOFF_AL  5120
#define SOFF_BH  10240
#define SOFF_BL  12800
#define STG_ELEMS 15360
#define MMA_SMEM_BYTES (2 * STG_ELEMS * 2)   // 61440

__global__ void __launch_bounds__(256)
mma_gemm_kernel(const __nv_bfloat16* __restrict__ AH, const __nv_bfloat16* __restrict__ AL,
                const __nv_bfloat16* __restrict__ WH, const __nv_bfloat16* __restrict__ WL,
                int kpad, int nChunks,
                const float* __restrict__ b1, const float* __restrict__ b2,
                float* __restrict__ Cf, __nv_bfloat16* __restrict__ CH,
                __nv_bfloat16* __restrict__ CL,
                int ldC, int M, int Nreal, int relu, int remapT) {
    extern __shared__ __align__(16) __nv_bfloat16 smbuf[];
    const uint32_t sb = smem_to_u32(smbuf);

    const int tid  = threadIdx.x;
    const int wid  = tid >> 5, lane = tid & 31;
    const int g    = lane >> 2, tg = lane & 3;
    const int m0   = (wid & 3) * 32;
    const int n0   = (wid >> 2) * 32;
    const int row0 = blockIdx.y * 128;
    const int col0 = blockIdx.x * 64;

    const int ar0 = tid >> 2, aseg = tid & 3;
    const int br  = tid >> 2, bseg = tid & 3;

    float d[2][4][4];
#pragma unroll
    for (int mi = 0; mi < 2; mi++)
#pragma unroll
        for (int ni = 0; ni < 4; ni++)
#pragma unroll
            for (int q = 0; q < 4; q++) d[mi][ni][q] = 0.f;

    auto load_chunk = [&](int ch, int stg) {
        const int kbase = ch * 32;
        const uint32_t base = sb + stg * (STG_ELEMS * 2);
#pragma unroll
        for (int i = 0; i < 2; i++) {
            int r = ar0 + i * 64;
            size_t go = (size_t)(row0 + r) * kpad + kbase + aseg * 8;
            uint32_t so = base + (r * 40 + aseg * 8) * 2;
            cpasync16(so, AH + go);
            cpasync16(so + SOFF_AL * 2, AL + go);
        }
        {
            size_t go = (size_t)(col0 + br) * kpad + kbase + bseg * 8;
            uint32_t so = base + (SOFF_BH + br * 40 + bseg * 8) * 2;
            cpasync16(so, WH + go);
            cpasync16(so + (SOFF_BL - SOFF_BH) * 2, WL + go);
        }
    };

    load_chunk(0, 0);
    CP_COMMIT();

    for (int ch = 0; ch < nChunks; ch++) {
        const int cur = ch & 1;
        if (ch + 1 < nChunks) load_chunk(ch + 1, cur ^ 1);
        CP_COMMIT();
        CP_WAIT1();
        __syncthreads();

        const __nv_bfloat16* sAH = smbuf + cur * STG_ELEMS;
        const __nv_bfloat16* sAL = sAH + SOFF_AL;
        const __nv_bfloat16* sBH = smbuf + cur * STG_ELEMS + SOFF_BH;
        const __nv_bfloat16* sBL = smbuf + cur * STG_ELEMS + SOFF_BL;

#pragma unroll
        for (int ks = 0; ks < 2; ks++) {
            const int kb = ks * 16;
            uint32_t aH[2][4], aL[2][4], bH[4][2], bL[4][2];
#pragma unroll
            for (int mi = 0; mi < 2; mi++) {
                int r = m0 + mi * 16 + g;
                aH[mi][0] = *(const uint32_t*)&sAH[r * 40 + kb + 2 * tg];
                aH[mi][1] = *(const uint32_t*)&sAH[(r + 8) * 40 + kb + 2 * tg];
                aH[mi][2] = *(const uint32_t*)&sAH[r * 40 + kb + 2 * tg + 8];
                aH[mi][3] = *(const uint32_t*)&sAH[(r + 8) * 40 + kb + 2 * tg + 8];
                aL[mi][0] = *(const uint32_t*)&sAL[r * 40 + kb + 2 * tg];
                aL[mi][1] = *(const uint32_t*)&sAL[(r + 8) * 40 + kb + 2 * tg];
                aL[mi][2] = *(const uint32_t*)&sAL[r * 40 + kb + 2 * tg + 8];
                aL[mi][3] = *(const uint32_t*)&sAL[(r + 8) * 40 + kb + 2 * tg + 8];
            }
#pragma unroll
            for (int ni = 0; ni < 4; ni++) {
                int r = n0 + ni * 8 + g;
                bH[ni][0] = *(const uint32_t*)&sBH[r * 40 + kb + 2 * tg];
                bH[ni][1] = *(const uint32_t*)&sBH[r * 40 + kb + 2 * tg + 8];
                bL[ni][0] = *(const uint32_t*)&sBL[r * 40 + kb + 2 * tg];
                bL[ni][1] = *(const uint32_t*)&sBL[r * 40 + kb + 2 * tg + 8];
            }
#pragma unroll
            for (int mi = 0; mi < 2; mi++)
#pragma unroll
                for (int ni = 0; ni < 4; ni++) {
                    mma16816(d[mi][ni], aH[mi], bH[ni]);
                    mma16816(d[mi][ni], aL[mi], bH[ni]);
                    mma16816(d[mi][ni], aH[mi], bL[ni]);
                }
        }
        __syncthreads();
    }

#pragma unroll
    for (int mi = 0; mi < 2; mi++) {
#pragma unroll
        for (int rr = 0; rr < 2; rr++) {
            int r = row0 + m0 + mi * 16 + g + rr * 8;
            if (r >= M) continue;
            size_t rowbase;
            if (remapT > 0) {
                int bb = r / remapT, tt = r - bb * remapT;
                rowbase = ((size_t)bb * (remapT + 1) + tt + 1) * (size_t)ldC;
            } else {
                rowbase = (size_t)r * ldC;
            }
#pragma unroll
            for (int ni = 0; ni < 4; ni++) {
#pragma unroll
                for (int cc = 0; cc < 2; cc++) {
                    int col = col0 + n0 + ni * 8 + 2 * tg + cc;
                    if (col >= Nreal) continue;
                    float v = d[mi][ni][rr * 2 + cc]
                            + (b1 ? __ldg(b1 + col) : 0.f) + (b2 ? __ldg(b2 + col) : 0.f);
                    if (relu) v = fmaxf(v, 0.f);
                    if (Cf) Cf[rowbase + col] = v;
                    if (CH) {
                        __nv_bfloat16 hi, lo; bf16_split(v, hi, lo);
                        CH[rowbase + col] = hi;
                        CL[rowbase + col] = lo;
                    }
                }
            }
        }
    }
}

// ---------------- persistent LSTM scan (HMMA phase-2) ----------------------
// Grid: 128 CTAs = 4 batch-groups(16 batches) x 32 hidden-tiles(16 hidden).
// Weights pre-split bf16 hi/lo in smem (stride 520 -> conflict-free frags).
// Per step: h fp32 -> bf16 hi/lo smem; warp w does k-slice [w*64,w*64+64)
// as m16 x n64 x k64 HMMA (3 split terms); frag->red; reduce+cell (fp32).
// Barrier: round-8 proven atomicAdd version.
#define SW_K     520
#define SOFF_WL  (64 * SW_K)               // 33280
#define SOFF_HH  (2 * 64 * SW_K)           // 66560
#define SOFF_HL  (SOFF_HH + 16 * SW_K)     // 74880
#define SCAN_BF16_ELEMS (SOFF_HL + 16 * SW_K)   // 83200
#define SCAN_RED_FLOATS (8 * 16 * 66)      // 8448
#define SCAN_SMEM_BYTES (SCAN_BF16_ELEMS * 2 + SCAN_RED_FLOATS * 4)  // 200192

__device__ __forceinline__ float sigf(float x) { return 1.f / (1.f + expf(-x)); }

__device__ __forceinline__ void group_barrier(unsigned* bar, int bg, unsigned target) {
    __threadfence();
    __syncthreads();
    if (threadIdx.x == 0) {
        atomicAdd(&bar[bg], 1u);
        while (atomicAdd(&bar[bg], 0u) < target) { }
        __threadfence();
    }
    __syncthreads();
}

__global__ void __launch_bounds__(256, 1)
lstm_scan_kernel(const float* __restrict__ gx, const float* __restrict__ Whh,
                 const float* __restrict__ h0, const float* __restrict__ c0,
                 __nv_bfloat16* __restrict__ hsH, __nv_bfloat16* __restrict__ hsL,
                 float* __restrict__ hT_out, float* __restrict__ cT_out,
                 float* __restrict__ hpub, unsigned* __restrict__ bar, int T) {
    extern __shared__ __align__(16) __nv_bfloat16 sm[];
    __nv_bfloat16* sWH = sm;                 // [64][520]
    __nv_bfloat16* sWL = sm + SOFF_WL;       // [64][520]
    __nv_bfloat16* sHH = sm + SOFF_HH;       // [16][520]
    __nv_bfloat16* sHL = sm + SOFF_HL;       // [16][520]
    float* red = (float*)(sm + SCAN_BF16_ELEMS);  // [8][16][66]

    const int tid = threadIdx.x;
    const int bg = blockIdx.x >> 5;
    const int ht = blockIdx.x & 31;
    const int B0 = bg * 16;
    const int J0 = ht * 16;
    const int w = tid >> 5;
    const int lane = tid & 31;
    const int g = lane >> 2, tg = lane & 3;

    // ---- load + split Whh slice into smem (once); n = gate*16 + j ----
    for (int idx = tid; idx < 64 * 512; idx += 256) {
        int n = idx >> 9, k = idx & 511;
        float v = Whh[(size_t)((n >> 4) * 512 + J0 + (n & 15)) * 512 + k];
        __nv_bfloat16 hi, lo; bf16_split(v, hi, lo);
        sWH[n * SW_K + k] = hi;
        sWL[n * SW_K + k] = lo;
    }

    // ---- init states ----
    const int ub = tid >> 4;            // batch within tile (0..15)
    const int uj = tid & 15;            // hidden within tile (0..15)
    float cval = c0 ? c0[(B0 + ub) * 512 + J0 + uj] : 0.f;
    float hval = h0 ? h0[(B0 + ub) * 512 + J0 + uj] : 0.f;
    hpub[32768 + (B0 + ub) * 512 + J0 + uj] = hval;   // parity-1 slot feeds t=0

    unsigned nbar = 1;
    group_barrier(bar, bg, nbar * 32);   // also covers weight-load visibility

    const int p1b = tid & 15;
    const int p1k = tid >> 4;

    const float* gxrow = gx + ((size_t)(B0 + ub) * T) * G4 + J0 + uj;
    __nv_bfloat16* hH = hsH ? hsH + ((size_t)(B0 + ub) * T) * 512 + J0 + uj : nullptr;
    __nv_bfloat16* hL = hsL ? hsL + ((size_t)(B0 + ub) * T) * 512 + J0 + uj : nullptr;

    for (int t = 0; t < T; ++t) {
        float pgi = gxrow[0], pgf = gxrow[512], pgg = gxrow[1024], pgo = gxrow[1536];

        const float* hsrc = hpub + (((t + 1) & 1) << 15);

        // phase 1: load h (fp32, L2-coherent), split to bf16 hi/lo smem
#pragma unroll
        for (int i = 0; i < 8; ++i) {
            int kq = p1k + (i << 4);                  // float4 index 0..127
            float4 hv = __ldcg((const float4*)(hsrc + (B0 + p1b) * 512 + (kq << 2)));
            __nv_bfloat16 hx, lx, hy, ly, hz, lz, hw, lw;
            bf16_split(hv.x, hx, lx); bf16_split(hv.y, hy, ly);
            bf16_split(hv.z, hz, lz); bf16_split(hv.w, hw, lw);
            int base = p1b * SW_K + (kq << 2);
            *(__nv_bfloat162*)&sHH[base]     = __halves2bfloat162(hx, hy);
            *(__nv_bfloat162*)&sHH[base + 2] = __halves2bfloat162(hz, hw);
            *(__nv_bfloat162*)&sHL[base]     = __halves2bfloat162(lx, ly);
            *(__nv_bfloat162*)&sHL[base + 2] = __halves2bfloat162(lz, lw);
        }
        __syncthreads();

        // phase 2: HMMA m16 x n64 x k64, bf16 split 3 terms
        float c[8][4];
#pragma unroll
        for (int ni = 0; ni < 8; ni++)
#pragma unroll
            for (int q = 0; q < 4; q++) c[ni][q] = 0.f;

        const int kb0 = w * 64;
#pragma unroll
        for (int ks = 0; ks < 4; ks++) {
            const int kb = kb0 + ks * 16;
            uint32_t aH[4], aL[4];
            aH[0] = *(const uint32_t*)&sHH[g * SW_K + kb + 2 * tg];
            aH[1] = *(const uint32_t*)&sHH[(g + 8) * SW_K + kb + 2 * tg];
            aH[2] = *(const uint32_t*)&sHH[g * SW_K + kb + 2 * tg + 8];
            aH[3] = *(const uint32_t*)&sHH[(g + 8) * SW_K + kb + 2 * tg + 8];
            aL[0] = *(const uint32_t*)&sHL[g * SW_K + kb + 2 * tg];
            aL[1] = *(const uint32_t*)&sHL[(g + 8) * SW_K + kb + 2 * tg];
            aL[2] = *(const uint32_t*)&sHL[g * SW_K + kb + 2 * tg + 8];
            aL[3] = *(const uint32_t*)&sHL[(g + 8) * SW_K + kb + 2 * tg + 8];
            uint32_t bH[8][2], bL[8][2];
#pragma unroll
            for (int ni = 0; ni < 8; ni++) {
                int r = ni * 8 + g;
                bH[ni][0] = *(const uint32_t*)&sWH[r * SW_K + kb + 2 * tg];
                bH[ni][1] = *(const uint32_t*)&sWH[r * SW_K + kb + 2 * tg + 8];
                bL[ni][0] = *(const uint32_t*)&sWL[r * SW_K + kb + 2 * tg];
                bL[ni][1] = *(const uint32_t*)&sWL[r * SW_K + kb + 2 * tg + 8];
            }
#pragma unroll
            for (int ni = 0; ni < 8; ni++) {
                mma16816(c[ni], aH, bH[ni]);
                mma16816(c[ni], aL, bH[ni]);
                mma16816(c[ni], aH, bL[ni]);
            }
        }

        // phase 3: fragments -> red[w][m][n] (pad 66)
#pragma unroll
        for (int ni = 0; ni < 8; ni++) {
            int nn = ni * 8 + 2 * tg;
            float2 v01 = make_float2(c[ni][0], c[ni][1]);
            float2 v23 = make_float2(c[ni][2], c[ni][3]);
            *(float2*)&red[w * 1056 + g * 66 + nn] = v01;
            *(float2*)&red[w * 1056 + (g + 8) * 66 + nn] = v23;
        }
        __syncthreads();

        // phase 4: reduce 8 k-slices, add gx, LSTM cell (thread = (ub,uj))
        float gsum[4];
#pragma unroll
        for (int gt = 0; gt < 4; gt++) {
            float v = 0.f;
#pragma unroll
            for (int s2 = 0; s2 < 8; s2++)
                v += red[s2 * 1056 + ub * 66 + gt * 16 + uj];
            gsum[gt] = v;
        }
        float gi = gsum[0] + pgi, gf = gsum[1] + pgf;
        float gg = gsum[2] + pgg, go = gsum[3] + pgo;

        float ig = sigf(gi), fg = sigf(gf), og_ = sigf(go), gt_ = tanhf(gg);
        cval = fg * cval + ig * gt_;
        hval = og_ * tanhf(cval);

        hpub[((t & 1) << 15) + (B0 + ub) * 512 + J0 + uj] = hval;
        if (hH) {
            __nv_bfloat16 hi, lo; bf16_split(hval, hi, lo);
            *hH = hi; *hL = lo; hH += 512; hL += 512;
        }
        gxrow += G4;

        ++nbar;
        group_barrier(bar, bg, nbar * 32);
    }

    hT_out[(B0 + ub) * 512 + J0 + uj] = hval;
    cT_out[(B0 + ub) * 512 + J0 + uj] = cval;
}

// ---------------- host orchestration ----------------
static __nv_bfloat16 *s_AH, *s_AL, *s_MH, *s_ML, *s_WH, *s_WL;

static void launch_mma(const __nv_bfloat16* AH, const __nv_bfloat16* AL,
                       int kpad, const float* b1, const float* b2,
                       float* Cf, __nv_bfloat16* CH, __nv_bfloat16* CL,
                       int ldC, int M, int Nreal, int relu, int remapT) {
    int mt = (M + 127) / 128;
    int nt = (Nreal + 63) / 64;
    int nChunks = kpad / 32;
    mma_gemm_kernel<<<dim3(nt, mt), 256, MMA_SMEM_BYTES>>>(
        AH, AL, s_WH, s_WL, kpad, nChunks, b1, b2, Cf, CH, CL, ldC, M, Nreal, relu, remapT);
}

static void launch_convw(const float* W, int N, int K, int kpad) {
    int Npad = ((N + 63) / 64) * 64;
    long n = (long)Npad * kpad;
    conv_w_kernel<<<(int)((n + 255) / 256), 256>>>(W, s_WH, s_WL, N, K, kpad, Npad);
}

extern "C" void kernel_launch(void* const* d_in, const int* in_sizes, int n_in,
                              void* d_out, int out_size) {
    (void)in_sizes; (void)n_in; (void)out_size;
    const float* x     = (const float*)d_in[0];
    const float* y     = (const float*)d_in[1];
    const float* eWih0 = (const float*)d_in[2];
    const float* eWhh0 = (const float*)d_in[3];
    const float* ebih0 = (const float*)d_in[4];
    const float* ebhh0 = (const float*)d_in[5];
    const float* eWih1 = (const float*)d_in[6];
    const float* eWhh1 = (const float*)d_in[7];
    const float* ebih1 = (const float*)d_in[8];
    const float* ebhh1 = (const float*)d_in[9];
    const float* dWih0 = (const float*)d_in[10];
    const float* dWhh0 = (const float*)d_in[11];
    const float* dbih0 = (const float*)d_in[12];
    const float* dbhh0 = (const float*)d_in[13];
    const float* dWih1 = (const float*)d_in[14];
    const float* dWhh1 = (const float*)d_in[15];
    const float* dbih1 = (const float*)d_in[16];
    const float* dbhh1 = (const float*)d_in[17];
    const float* clsW1 = (const float*)d_in[18];
    const float* clsb1 = (const float*)d_in[19];
    const float* clsW2 = (const float*)d_in[20];
    const float* clsb2 = (const float*)d_in[21];
    float* out = (float*)d_out;

    float *gx, *hpub, *hT0, *cT0, *hT1, *cT1, *hTd, *cTd;
    unsigned* bar;
    cudaGetSymbolAddress((void**)&gx,   g_gx);
    cudaGetSymbolAddress((void**)&hpub, g_hpub);
    cudaGetSymbolAddress((void**)&hT0,  g_hT0);
    cudaGetSymbolAddress((void**)&cT0,  g_cT0);
    cudaGetSymbolAddress((void**)&hT1,  g_hT1);
    cudaGetSymbolAddress((void**)&cT1,  g_cT1);
    cudaGetSymbolAddress((void**)&hTd,  g_hTd);
    cudaGetSymbolAddress((void**)&cTd,  g_cTd);
    cudaGetSymbolAddress((void**)&bar,  g_bar);
    cudaGetSymbolAddress((void**)&s_AH, g_AH);
    cudaGetSymbolAddress((void**)&s_AL, g_AL);
    cudaGetSymbolAddress((void**)&s_MH, g_MH);
    cudaGetSymbolAddress((void**)&s_ML, g_ML);
    cudaGetSymbolAddress((void**)&s_WH, g_WHb);
    cudaGetSymbolAddress((void**)&s_WL, g_WLb);

    cudaFuncSetAttribute(lstm_scan_kernel,
                         cudaFuncAttributeMaxDynamicSharedMemorySize, SCAN_SMEM_BYTES);
    cudaFuncSetAttribute(mma_gemm_kernel,
                         cudaFuncAttributeMaxDynamicSharedMemorySize, MMA_SMEM_BYTES);

    const int ME  = MROWS_MAX;   // 65600
    const int MDN = MD_ROWS;     // 65472

    // ---------------- encoder ----------------
    {
        long n = (long)BATCH * T_ENC * 192;
        pad_shift_bf16_kernel<<<(int)((n + 255) / 256), 256>>>(x, s_AH, s_AL, 1024, T_ENC, 1024);
    }
    launch_convw(eWih0, G4, DIN, 192);
    launch_mma(s_AH, s_AL, 192, ebih0, ebhh0, gx, nullptr, nullptr, G4, ME, G4, 0, 0);
    reset_bar_kernel<<<1, 32>>>(bar);
    lstm_scan_kernel<<<128, 256, SCAN_SMEM_BYTES>>>(gx, eWhh0, nullptr, nullptr,
                                                    s_AH, s_AL, hT0, cT0, hpub, bar, T_ENC);
    launch_convw(eWih1, G4, HID, 512);
    launch_mma(s_AH, s_AL, 512, ebih1, ebhh1, gx, nullptr, nullptr, G4, ME, G4, 0, 0);
    reset_bar_kernel<<<1, 32>>>(bar);
    lstm_scan_kernel<<<128, 256, SCAN_SMEM_BYTES>>>(gx, eWhh1, nullptr, nullptr,
                                                    nullptr, nullptr, hT1, cT1, hpub, bar, T_ENC);

    // ---------------- decoder ----------------
    {
        long n = (long)BATCH * T_DEC * 192;
        pad_shift_bf16_kernel<<<(int)((n + 255) / 256), 256>>>(y, s_AH, s_AL, 1024, T_DEC, 1022);
    }
    launch_convw(dWih0, G4, DIN, 192);
    launch_mma(s_AH, s_AL, 192, dbih0, dbhh0, gx, nullptr, nullptr, G4, MDN, G4, 0, 0);
    reset_bar_kernel<<<1, 32>>>(bar);
    lstm_scan_kernel<<<128, 256, SCAN_SMEM_BYTES>>>(gx, dWhh0, hT0, cT0,
                                                    s_AH, s_AL, hTd, cTd, hpub, bar, T_DEC);
    launch_convw(dWih1, G4, HID, 512);
    launch_mma(s_AH, s_AL, 512, dbih1, dbhh1, gx, nullptr, nullptr, G4, MDN, G4, 0, 0);
    reset_bar_kernel<<<1, 32>>>(bar);
    lstm_scan_kernel<<<128, 256, SCAN_SMEM_BYTES>>>(gx, dWhh1, hT1, cT1,
                                                    s_AH, s_AL, hTd, cTd, hpub, bar, T_DEC);

    // ---------------- classifier ----------------
    launch_convw(clsW1, 256, HID, 512);
    launch_mma(s_AH, s_AL, 512, clsb1, nullptr, nullptr, s_MH, s_ML, 256, MDN, 256, 1, 0);
    launch_convw(clsW2, DIN, 256, 256);
    launch_mma(s_MH, s_ML, 256, clsb2, nullptr, out, nullptr, nullptr, DIN, MDN, DIN, 0, T_DEC);
    zero_t0_kernel<<<(BATCH * DIN + 255) / 256, 256>>>(out);
}